// round 9
// baseline (speedup 1.0000x reference)
#include <cuda_runtime.h>
#include <cuda_fp16.h>
#include <cstdint>

#define B_     4096
#define N_IN   512
#define H1     1536
#define H2     1536
#define N_OUT  512
#define NODES  3584          // N_IN + H1 + H2
#define CAP    128           // bucket capacity per dst (Poisson(32), max ~66)
#define TBLOCKS 2048         // transpose blocks in fused setup kernel (16 x 128)

typedef unsigned long long u64;

// ---------------- static device scratch (no allocations) ----------------
__device__ __align__(16) __half g_nvTh[NODES * B_];      // 29.4 MB
__device__ int  g_cnt[NODES];        // zero at load; re-zeroed by lvl2/lvl3 each call
__device__ __align__(16) int2 g_bpack[NODES * CAP];      // (src, w-bits); slots >= cnt stay 0

// ---------------- packed f32x2 helpers ----------------
__device__ __forceinline__ u64 pack2(float x, float y) {
    u64 r; asm("mov.b64 %0, {%1, %2};" : "=l"(r) : "f"(x), "f"(y)); return r;
}
__device__ __forceinline__ float2 unpack2(u64 v) {
    float2 f; asm("mov.b64 {%0, %1}, %2;" : "=f"(f.x), "=f"(f.y) : "l"(v)); return f;
}
__device__ __forceinline__ void ffma2(u64& acc, u64 a, u64 b) {
    asm("fma.rn.f32x2 %0, %1, %2, %0;" : "+l"(acc) : "l"(a), "l"(b));
}
__device__ __forceinline__ u64 cvt2(uint32_t h2) {
    float2 f = __half22float2(*reinterpret_cast<const __half2*>(&h2));
    return pack2(f.x, f.y);
}

// ---------------- fused setup: transpose x -> fp16 nvT  +  bucket build ----
__global__ void setup_kernel(const float* __restrict__ x,
                             const int* __restrict__ src0, const int* __restrict__ dst0,
                             const float* __restrict__ w0, int E1,
                             const int* __restrict__ src1, const int* __restrict__ dst1,
                             const float* __restrict__ w1, int E2,
                             const int* __restrict__ src2, const int* __restrict__ dst2,
                             const float* __restrict__ w2, int E3) {
    const int tid = threadIdx.x;
    if (blockIdx.x < TBLOCKS) {
        __shared__ float tile[32][33];
        const int bx = (blockIdx.x & 15) * 32;   // node dim
        const int by = (blockIdx.x >> 4) * 32;   // batch dim
        const int tx = tid & 31, ty = tid >> 5;  // 32 x 8
#pragma unroll
        for (int i = 0; i < 32; i += 8)
            tile[ty + i][tx] = x[(size_t)(by + ty + i) * N_IN + bx + tx];
        __syncthreads();
#pragma unroll
        for (int i = 0; i < 32; i += 8)
            g_nvTh[(size_t)(bx + ty + i) * B_ + by + tx] = __float2half(tile[tx][ty + i]);
        return;
    }
    // ---- bucket part: 4 consecutive edges per thread ----
    int i0 = ((blockIdx.x - TBLOCKS) * 256 + tid) * 4;
    const int Etot = E1 + E2 + E3;
    if (i0 >= Etot) return;
    const int *sp, *dp; const float* wp; int dbase, j0;
    if (i0 < E1)           { sp = src0; dp = dst0; wp = w0; dbase = 0;       j0 = i0; }
    else if (i0 < E1 + E2) { sp = src1; dp = dst1; wp = w1; dbase = H1;      j0 = i0 - E1; }
    else                   { sp = src2; dp = dst2; wp = w2; dbase = H1 + H2; j0 = i0 - E1 - E2; }
    int4   s = *reinterpret_cast<const int4*>(sp + j0);
    int4   d = *reinterpret_cast<const int4*>(dp + j0);
    float4 w = *reinterpret_cast<const float4*>(wp + j0);
#pragma unroll
    for (int k = 0; k < 4; k++) {
        int sk = (&s.x)[k];
        int dk = dbase + (&d.x)[k];
        float wk = (&w.x)[k];
        int c = atomicAdd(&g_cnt[dk], 1);
        if (c < CAP)
            g_bpack[(size_t)dk * CAP + c] = make_int2(sk, __float_as_int(wk));
    }
}

// ---------------- sparse level kernel ----------------
// One CTA per dst node; thread t owns 8-col strips at t*8 and t*8+2048.
// fp16 values, f32x2 accumulate. Buckets are processed in uniform 4-edge
// blocks: slots >= cnt are zero-filled (w=0) so pads contribute nothing.
// LVL: 1 = h1 (fp16 out), 2 = h2 (fp16 out, zeros cnt[0,H1)),
//      3 = output (direct transposed fp32 stores to d_out, zeros cnt[H1,NODES)).
__device__ __forceinline__ void strip_fma(u64* a, u64 W, uint4 v) {
    ffma2(a[0], W, cvt2(v.x));
    ffma2(a[1], W, cvt2(v.y));
    ffma2(a[2], W, cvt2(v.z));
    ffma2(a[3], W, cvt2(v.w));
}

template <int LVL>
__global__ void __launch_bounds__(256)
level_kernel(__half* __restrict__ outh, float* __restrict__ outf) {
    const int d = blockIdx.x;
    const int t = threadIdx.x;
    constexpr int cbase = (LVL == 1) ? 0 : (LVL == 2) ? H1 : H1 + H2;

    int cnt = g_cnt[cbase + d];
    if (LVL == 3) {
        __syncthreads();   // all reads of cnt[cbase+d] done before self-zero
        if (t == 0) {
            g_cnt[H1 + d]        = 0;   // level-2 range (1536 = 3 x 512)
            g_cnt[H1 + 512 + d]  = 0;
            g_cnt[H1 + 1024 + d] = 0;
            g_cnt[H1 + H2 + d]   = 0;   // own entry
        }
    } else if (LVL == 2) {
        if (t == 0) g_cnt[d] = 0;       // level-1 range (H2 == H1 blocks)
    }

    if (cnt > CAP) cnt = CAP;
    const int cntUp = (cnt + 3) & ~3;   // pads are zero-weight, safe
    const int2* bp = g_bpack + (size_t)(cbase + d) * CAP;

    const int c0 = t * 8;
    const __half* __restrict__ nvTh = g_nvTh;

    u64 aA[4] = {0, 0, 0, 0};
    u64 aB[4] = {0, 0, 0, 0};

    // metadata prefetch, 1 block ahead
    int4 m0, m1;
    if (cntUp > 0) {
        m0 = *reinterpret_cast<const int4*>(bp);       // s0,w0,s1,w1
        m1 = *reinterpret_cast<const int4*>(bp + 2);   // s2,w2,s3,w3
    }
    for (int e = 0; e < cntUp; e += 4) {
        const __half* r0 = nvTh + (size_t)m0.x * B_ + c0;
        const __half* r1 = nvTh + (size_t)m0.z * B_ + c0;
        const __half* r2 = nvTh + (size_t)m1.x * B_ + c0;
        const __half* r3 = nvTh + (size_t)m1.z * B_ + c0;
        uint4 v0a = *reinterpret_cast<const uint4*>(r0);
        uint4 v0b = *reinterpret_cast<const uint4*>(r0 + 2048);
        uint4 v1a = *reinterpret_cast<const uint4*>(r1);
        uint4 v1b = *reinterpret_cast<const uint4*>(r1 + 2048);
        uint4 v2a = *reinterpret_cast<const uint4*>(r2);
        uint4 v2b = *reinterpret_cast<const uint4*>(r2 + 2048);
        uint4 v3a = *reinterpret_cast<const uint4*>(r3);
        uint4 v3b = *reinterpret_cast<const uint4*>(r3 + 2048);
        u64 W0 = pack2(__int_as_float(m0.y), __int_as_float(m0.y));
        u64 W1 = pack2(__int_as_float(m0.w), __int_as_float(m0.w));
        u64 W2 = pack2(__int_as_float(m1.y), __int_as_float(m1.y));
        u64 W3 = pack2(__int_as_float(m1.w), __int_as_float(m1.w));
        if (e + 4 < cntUp) {
            m0 = *reinterpret_cast<const int4*>(bp + e + 4);
            m1 = *reinterpret_cast<const int4*>(bp + e + 6);
        }
        strip_fma(aA, W0, v0a);  strip_fma(aB, W0, v0b);
        strip_fma(aA, W1, v1a);  strip_fma(aB, W1, v1b);
        strip_fma(aA, W2, v2a);  strip_fma(aB, W2, v2b);
        strip_fma(aA, W3, v3a);  strip_fma(aB, W3, v3b);
    }

    // ---- relu + store ----
#pragma unroll
    for (int s = 0; s < 2; s++) {
        float r[8];
        u64* acc = (s == 0) ? aA : aB;
#pragma unroll
        for (int j = 0; j < 4; j++) {
            float2 f = unpack2(acc[j]);
            r[2 * j]     = fmaxf(f.x, 0.f);
            r[2 * j + 1] = fmaxf(f.y, 0.f);
        }
        const int cc = c0 + s * 2048;
        if (LVL == 3) {
            // direct transposed store: out[b][d], b = cc..cc+7
            float* po = outf + (size_t)cc * N_OUT + d;
#pragma unroll
            for (int j = 0; j < 8; j++)
                po[(size_t)j * N_OUT] = r[j];
        } else {
            uint4 o; __half2 h;
            h = __floats2half2_rn(r[0], r[1]); o.x = *reinterpret_cast<uint32_t*>(&h);
            h = __floats2half2_rn(r[2], r[3]); o.y = *reinterpret_cast<uint32_t*>(&h);
            h = __floats2half2_rn(r[4], r[5]); o.z = *reinterpret_cast<uint32_t*>(&h);
            h = __floats2half2_rn(r[6], r[7]); o.w = *reinterpret_cast<uint32_t*>(&h);
            *reinterpret_cast<uint4*>(outh + (size_t)d * B_ + cc) = o;
        }
    }
}

// ---------------- launch ----------------
extern "C" void kernel_launch(void* const* d_in, const int* in_sizes, int n_in,
                              void* d_out, int out_size) {
    const float* x    = (const float*)d_in[0];
    const int*   src0 = (const int*)  d_in[1];
    const int*   dst0 = (const int*)  d_in[2];
    const float* w0   = (const float*)d_in[3];
    const int*   src1 = (const int*)  d_in[4];
    const int*   dst1 = (const int*)  d_in[5];
    const float* w1   = (const float*)d_in[6];
    const int*   src2 = (const int*)  d_in[7];
    const int*   dst2 = (const int*)  d_in[8];
    const float* w2   = (const float*)d_in[9];
    float* out = (float*)d_out;

    __half* pnvTh; cudaGetSymbolAddress((void**)&pnvTh, g_nvTh);

    const int E1 = in_sizes[1], E2 = in_sizes[4], E3 = in_sizes[7];
    const int Etot = E1 + E2 + E3;

    // 1) fused setup: transpose x (fp32->fp16) + build edge buckets
    {
        int bucketBlocks = (Etot + 1023) / 1024;
        setup_kernel<<<TBLOCKS + bucketBlocks, 256>>>(
            x, src0, dst0, w0, E1, src1, dst1, w1, E2, src2, dst2, w2, E3);
    }

    // 2) sparse levels (one CTA per dst node); lvl3 writes d_out transposed
    level_kernel<1><<<H1, 256>>>(pnvTh + (size_t)N_IN * B_,        nullptr);
    level_kernel<2><<<H2, 256>>>(pnvTh + (size_t)(N_IN + H1) * B_, nullptr);
    level_kernel<3><<<N_OUT, 256>>>(nullptr, out);
}